// round 9
// baseline (speedup 1.0000x reference)
#include <cuda_runtime.h>
#include <cuda_bf16.h>
#include <math.h>
#include <stdint.h>

#define NB 4096
#define FEATN 30

// ---------------- scratch (static device globals; no allocation) ----------------
__device__ float g_fvs[NB * FEATN];
__device__ float g_fvd[NB * FEATN];
__device__ float g_fps[NB * FEATN];
__device__ float g_fpd[NB * FEATN];
__device__ float g_y30[NB * FEATN];
// conv2 weight tiles, bf16 hi/lo, SW128-swizzled images: 10 tiles x 4096 B
// tiles 0..4 = Wh for k=0..4 ; tiles 5..9 = Wl for k=0..4. Tile: [n=32][c=64] bf16.
__device__ __align__(16) unsigned char g_w2t[10 * 4096];

// ---------------- f32x2 helpers ----------------
typedef unsigned long long ull_t;
__device__ __forceinline__ ull_t f2pack(float lo, float hi) {
    ull_t r; asm("mov.b64 %0, {%1,%2};" : "=l"(r) : "f"(lo), "f"(hi)); return r;
}
__device__ __forceinline__ ull_t f2dup(float v) { return f2pack(v, v); }
__device__ __forceinline__ void f2fma(ull_t& d, ull_t a, ull_t b) {
    asm("fma.rn.f32x2 %0, %1, %2, %0;" : "+l"(d) : "l"(a), "l"(b));
}
__device__ __forceinline__ void f2unpack(ull_t v, float& lo, float& hi) {
    asm("mov.b64 {%0,%1}, %2;" : "=f"(lo), "=f"(hi) : "l"(v));
}

// ---------------- warp-MMA helpers (sm_80-path, legal on compute_103) ----------
__device__ __forceinline__ uint32_t smem_u32(const void* p) {
    uint32_t a;
    asm("{ .reg .u64 t; cvta.to.shared.u64 t, %1; cvt.u32.u64 %0, t; }" : "=r"(a) : "l"(p));
    return a;
}
__device__ __forceinline__ uint32_t sw128(uint32_t o) { return o ^ ((o >> 3) & 0x70); }

__device__ __forceinline__ void ldmx4(uint32_t* r, uint32_t addr) {
    asm volatile("ldmatrix.sync.aligned.m8n8.x4.shared.b16 {%0,%1,%2,%3}, [%4];"
                 : "=r"(r[0]), "=r"(r[1]), "=r"(r[2]), "=r"(r[3]) : "r"(addr));
}
__device__ __forceinline__ void ldmx2(uint32_t* r, uint32_t addr) {
    asm volatile("ldmatrix.sync.aligned.m8n8.x2.shared.b16 {%0,%1}, [%2];"
                 : "=r"(r[0]), "=r"(r[1]) : "r"(addr));
}
__device__ __forceinline__ void mma16816(float* d, const uint32_t* a, const uint32_t* b) {
    asm volatile("mma.sync.aligned.m16n8k16.row.col.f32.bf16.bf16.f32 "
                 "{%0,%1,%2,%3}, {%4,%5,%6,%7}, {%8,%9}, {%0,%1,%2,%3};"
                 : "+f"(d[0]), "+f"(d[1]), "+f"(d[2]), "+f"(d[3])
                 : "r"(a[0]), "r"(a[1]), "r"(a[2]), "r"(a[3]), "r"(b[0]), "r"(b[1]));
}

// =======================================================================
// Prep: build bf16 hi/lo SW128 tile images of conv2 weights.
// W2: [30][64][5] row-major.  Tile (h*5+k): byte sw128(n*128 + c*2) = bf16.
// =======================================================================
__global__ void prep_w2t(const float* __restrict__ W2) {
    int i = blockIdx.x * 256 + threadIdx.x;       // 10*32*64 = 20480
    if (i < 20480) {
        int tile = i >> 11;                        // 0..9
        int rem  = i & 2047;
        int n = rem >> 6, c = rem & 63;
        int half = tile / 5, k = tile % 5;
        float w = (n < 30) ? W2[n * 320 + c * 5 + k] : 0.f;
        __nv_bfloat16 wh = __float2bfloat16(w);
        __nv_bfloat16 val = half ? __float2bfloat16(w - __bfloat162float(wh)) : wh;
        *reinterpret_cast<__nv_bfloat16*>(
            g_w2t + tile * 4096 + sw128((uint32_t)(n * 128 + c * 2))) = val;
    }
}

// =======================================================================
// Encode kernel (unchanged): conv1d(3->64,K=3)+ReLU+mean + 2 heads.
// =======================================================================
__global__ __launch_bounds__(256) void encode_kernel(
    const float* __restrict__ S_V, const float* __restrict__ S_P,
    const float* __restrict__ Wc_v, const float* __restrict__ bc_v,
    const float* __restrict__ Ws_v, const float* __restrict__ bs_v,
    const float* __restrict__ Wd_v, const float* __restrict__ bd_v,
    const float* __restrict__ Wc_p, const float* __restrict__ bc_p,
    const float* __restrict__ Ws_p, const float* __restrict__ bs_p,
    const float* __restrict__ Wd_p, const float* __restrict__ bd_p)
{
    __shared__ __align__(16) float xs[3][1032];
    __shared__ float part[64][9];
    __shared__ float hsh[64];

    const int tid = threadIdx.x;
    const int b   = blockIdx.x;
    const int mo  = blockIdx.y;

    const float* S   = mo ? S_P  : S_V;
    const float* Wc  = mo ? Wc_p : Wc_v;
    const float* bc  = mo ? bc_p : bc_v;
    const float* Ws  = mo ? Ws_p : Ws_v;
    const float* bsv = mo ? bs_p : bs_v;
    const float* Wd  = mo ? Wd_p : Wd_v;
    const float* bdv = mo ? bd_p : bd_v;
    float* fs_out = mo ? g_fps : g_fvs;
    float* fd_out = mo ? g_fpd : g_fvd;

    if (tid < 24) xs[tid / 8][1024 + (tid & 7)] = 0.f;
    const float* Sb = S + (size_t)b * 3072;
    for (int i = tid; i < 3072; i += 256) xs[i % 3][i / 3] = Sb[i];
    __syncthreads();

    const int pg = tid >> 3;
    const int tg = tid & 7;
    const int o0 = pg * 2;

    ull_t WU[9];
#pragma unroll
    for (int i = 0; i < 9; i++)
        WU[i] = f2pack(Wc[o0 * 9 + i], Wc[o0 * 9 + 9 + i]);
    const ull_t Bp = f2pack(bc[o0], bc[o0 + 1]);

    float s0 = 0.f, s1 = 0.f;
    for (int m = 0; m < 32; m++) {
        const int t0 = 4 * tg + 32 * m;
        ull_t A[4] = {Bp, Bp, Bp, Bp};
#pragma unroll
        for (int c = 0; c < 3; c++) {
            float4 qa = *(const float4*)&xs[c][t0];
            float2 qb = *(const float2*)&xs[c][t0 + 4];
            ull_t X[6];
            X[0] = f2dup(qa.x); X[1] = f2dup(qa.y); X[2] = f2dup(qa.z);
            X[3] = f2dup(qa.w); X[4] = f2dup(qb.x); X[5] = f2dup(qb.y);
#pragma unroll
            for (int k = 0; k < 3; k++) {
                const ull_t W = WU[c * 3 + k];
#pragma unroll
                for (int p = 0; p < 4; p++) f2fma(A[p], X[p + k], W);
            }
        }
        float u[4], v[4];
#pragma unroll
        for (int p = 0; p < 4; p++) f2unpack(A[p], u[p], v[p]);
        if (t0 + 3 < 1022) {
#pragma unroll
            for (int p = 0; p < 4; p++) { s0 += fmaxf(u[p], 0.f); s1 += fmaxf(v[p], 0.f); }
        } else {
#pragma unroll
            for (int p = 0; p < 4; p++)
                if (t0 + p < 1022) { s0 += fmaxf(u[p], 0.f); s1 += fmaxf(v[p], 0.f); }
        }
    }
    part[o0][tg] = s0; part[o0 + 1][tg] = s1;
    __syncthreads();

    if (tid < 64) {
        float s = 0.f;
#pragma unroll
        for (int g = 0; g < 8; g++) s += part[tid][g];
        hsh[tid] = s * (1.f / 1022.f);
    }
    __syncthreads();

    if (tid < 60) {
        const int  j2 = tid % 30;
        const bool first = tid < 30;
        const float* Wm = first ? Ws : Wd;
        float s = first ? bsv[j2] : bdv[j2];
        for (int i = 0; i < 64; i++) s = fmaf(hsh[i], Wm[i * 30 + j2], s);
        if (first) fs_out[b * 30 + j2] = s;
        else       fd_out[b * 30 + j2] = s;
    }
}

// =======================================================================
// Physical-model kernel:
//   conv1 (f32x2) -> p1 bf16 hi/lo, t-major [256][64] SW128 smem
//   conv2 via warp mma.sync.m16n8k16 bf16 (3-product emulated fp32):
//     A (p1) fragments register-resident, shared by all 5 kernel shifts;
//     per shift k: G_k = p1 x W2_k, accumulated shifted into conv_out smem.
//   maxpool4 + mean -> y30.
// One block per sample, 512 threads (16 warps = 16 M-tiles), ~139 KB smem.
// =======================================================================
#define XS_OFF      0u        /* floats, aliases WBUF (dead after conv1) */
#define WBUF_OFF    0u        /* 40960 B, 10 x 4096 */
#define P1H_OFF     40960u    /* 32768 B */
#define P1L_OFF     73728u    /* 32768 B */
#define CO_OFF      106496u   /* conv_out: 256 x 33 floats = 33792 B */
#define PART_OFF    140288u   /* 480 floats */
#define PHYS_SMEM   142208
#define COSTR       33

__global__ __launch_bounds__(512) void phys_kernel(
    const float* __restrict__ S_P1,
    const float* __restrict__ W1, const float* __restrict__ b1,
    const float* __restrict__ b2)
{
    extern __shared__ __align__(16) unsigned char smraw[];
    const uint32_t smb = smem_u32(smraw);
    float* xs = (float*)(smraw + XS_OFF);
    float* conv_out = (float*)(smraw + CO_OFF);
    float* part = (float*)(smraw + PART_OFF);

    const int tid  = threadIdx.x;
    const int b    = blockIdx.x;
    const int wid  = tid >> 5;
    const int lane = tid & 31;

    const float* Sb = S_P1 + (size_t)b * 3072;
    for (int i = tid; i < 3072; i += 512) xs[(i % 3) * 1032 + i / 3] = Sb[i];
    __syncthreads();

    // -------- conv1 (K=5, C=3, O=64) + maxpool4, o-pair f32x2, bf16 hi/lo out --
    {
        const int pg = tid >> 4;
        const int tg = tid & 15;
        const int o0 = pg * 2;
        ull_t WU[15];
#pragma unroll
        for (int i = 0; i < 15; i++)
            WU[i] = f2pack(W1[o0 * 15 + i], W1[o0 * 15 + 15 + i]);
        const ull_t Bp = f2pack(b1[o0], b1[o0 + 1]);

        for (int m = 0; m < 16; m++) {
            const int j = tg + m * 16;
            if (j < 255) {
                const int t0 = 4 * j;
                ull_t A[4] = {Bp, Bp, Bp, Bp};
#pragma unroll
                for (int c = 0; c < 3; c++) {
                    const float* xr = xs + c * 1032 + t0;
                    float4 qa = *(const float4*)xr;
                    float4 qb = *(const float4*)(xr + 4);
                    ull_t X[8];
                    X[0] = f2dup(qa.x); X[1] = f2dup(qa.y); X[2] = f2dup(qa.z);
                    X[3] = f2dup(qa.w); X[4] = f2dup(qb.x); X[5] = f2dup(qb.y);
                    X[6] = f2dup(qb.z); X[7] = f2dup(qb.w);
#pragma unroll
                    for (int k = 0; k < 5; k++) {
                        const ull_t W = WU[c * 5 + k];
#pragma unroll
                        for (int p = 0; p < 4; p++) f2fma(A[p], X[p + k], W);
                    }
                }
                float u[4], v[4];
#pragma unroll
                for (int p = 0; p < 4; p++) f2unpack(A[p], u[p], v[p]);
                const float pa = fmaxf(fmaxf(u[0], u[1]), fmaxf(u[2], u[3]));
                const float pb = fmaxf(fmaxf(v[0], v[1]), fmaxf(v[2], v[3]));
                __nv_bfloat16 h0 = __float2bfloat16(pa);
                __nv_bfloat16 h1 = __float2bfloat16(pb);
                __nv_bfloat16 l0 = __float2bfloat16(pa - __bfloat162float(h0));
                __nv_bfloat16 l1 = __float2bfloat16(pb - __bfloat162float(h1));
                const uint32_t off = sw128((uint32_t)(j * 128 + o0 * 2));
                *reinterpret_cast<__nv_bfloat162*>(smraw + P1H_OFF + off) =
                    __halves2bfloat162(h0, h1);
                *reinterpret_cast<__nv_bfloat162*>(smraw + P1L_OFF + off) =
                    __halves2bfloat162(l0, l1);
            }
        }
    }
    // zero p1 row 255 (unwritten)
    if (tid < 32) {
        const uint32_t off = sw128((uint32_t)(255 * 128 + tid * 4));
        *reinterpret_cast<uint32_t*>(smraw + P1H_OFF + off) = 0u;
        *reinterpret_cast<uint32_t*>(smraw + P1L_OFF + off) = 0u;
    }
    __syncthreads();

    // -------- copy conv2 weight tiles into smem (xs region is dead now) -------
    {
        const uint4* gw = (const uint4*)g_w2t;
        uint4* swp = (uint4*)(smraw + WBUF_OFF);
        for (int i = tid; i < 2560; i += 512) swp[i] = gw[i];
    }
    __syncthreads();

    // -------- load A fragments once (shared across all 5 shifts) --------------
    // warp w owns M-rows [w*16, w*16+16)
    uint32_t Ah[4][4], Al[4][4];
    {
        const uint32_t row  = (uint32_t)(wid * 16 + (lane & 15));
        const uint32_t koff = (uint32_t)((lane >> 4) * 16);
#pragma unroll
        for (int ks = 0; ks < 4; ks++) {
            const uint32_t o = sw128(row * 128 + (uint32_t)ks * 32 + koff);
            ldmx4(Ah[ks], smb + P1H_OFF + o);
            ldmx4(Al[ks], smb + P1L_OFF + o);
        }
    }

    // -------- conv2: 5 shifts x 4 n-tiles x (4 kslices x 3 products) MMAs ----
    const uint32_t bn    = (uint32_t)(lane & 7) * 128;
    const uint32_t bkoff = (uint32_t)((lane >> 3) & 1) * 16;
    const int m0r = wid * 16 + (lane >> 2);
    const int n0c = (lane & 3) * 2;

#pragma unroll
    for (int k = 0; k < 5; k++) {
#pragma unroll
        for (int nt = 0; nt < 4; nt++) {
            float d[4] = {0.f, 0.f, 0.f, 0.f};
            const uint32_t bbase_h = smb + WBUF_OFF + (uint32_t)k * 4096;
            const uint32_t bbase_l = bbase_h + 5u * 4096;
            const uint32_t brow = bn + (uint32_t)nt * 1024;   // (nt*8+lane&7)*128
#pragma unroll
            for (int ks = 0; ks < 4; ks++) {
                const uint32_t bo = sw128(brow + (uint32_t)ks * 32 + bkoff);
                uint32_t bh[2], bl[2];
                ldmx2(bh, bbase_h + bo);
                ldmx2(bl, bbase_l + bo);
                mma16816(d, Ah[ks], bh);
                mma16816(d, Al[ks], bh);
                mma16816(d, Ah[ks], bl);
            }
            // epilogue: G_k[row] contributes to conv_out[row - k]
            const int n0 = nt * 8 + n0c;
            const int t0 = m0r - k;
            const int t1 = m0r + 8 - k;
            if (k == 0) {
                conv_out[t0 * COSTR + n0]     = d[0];
                conv_out[t0 * COSTR + n0 + 1] = d[1];
                conv_out[t1 * COSTR + n0]     = d[2];
                conv_out[t1 * COSTR + n0 + 1] = d[3];
            } else {
                if (t0 >= 0) {
                    conv_out[t0 * COSTR + n0]     += d[0];
                    conv_out[t0 * COSTR + n0 + 1] += d[1];
                }
                if (t1 <= 250) {
                    conv_out[t1 * COSTR + n0]     += d[2];
                    conv_out[t1 * COSTR + n0 + 1] += d[3];
                }
            }
        }
        __syncthreads();   // pass k fully written before pass k+1 RMW
    }

    // -------- maxpool4 (62 windows over t=0..247) + mean ----------------------
    if (tid < 480) {
        const int n = tid >> 4, jg = tid & 15;
        float s = 0.f;
#pragma unroll
        for (int j = jg; j < 62; j += 16) {
            const float* cr = conv_out + 4 * j * COSTR + n;
            float mx = fmaxf(fmaxf(cr[0], cr[COSTR]),
                             fmaxf(cr[2 * COSTR], cr[3 * COSTR]));
            s += mx;
        }
        part[n * 16 + jg] = s;
    }
    __syncthreads();
    if (tid < 30) {
        float s = 0.f;
#pragma unroll
        for (int g = 0; g < 16; g++) s += part[tid * 16 + g];
        g_y30[b * 30 + tid] = s * (1.f / 62.f) + b2[tid];
    }
}

// =======================================================================
// Fusion kernel (unchanged).
// =======================================================================
__global__ __launch_bounds__(256) void fuse_kernel(
    const int* __restrict__ pairs,
    const float* __restrict__ Wsp, const float* __restrict__ bsp,
    const float* __restrict__ Wa, const float* __restrict__ ba,
    const float* __restrict__ Wf, const float* __restrict__ bf,
    float* __restrict__ out)
{
    __shared__ float Wsp_s[900], bsp_s[30], Wa_s[5760], ba_s[192], Wf_s[128], bf_s[4];
    __shared__ float ain[8][4][32];

    const int tid = threadIdx.x;
    for (int i = tid; i < 900; i += 256) Wsp_s[i] = Wsp[i];
    for (int i = tid; i < 5760; i += 256) Wa_s[i] = Wa[i];
    if (tid < 30)  bsp_s[tid] = bsp[tid];
    if (tid < 192) ba_s[tid]  = ba[tid];
    if (tid < 128) Wf_s[tid]  = Wf[tid];
    if (tid < 4)   bf_s[tid]  = bf[tid];
    __syncthreads();

    const int warp = tid >> 5, lane = tid & 31;
    const int b = blockIdx.x * 8 + warp;

    float fvs = 0.f, fps = 0.f, fvd = 0.f, fpd = 0.f, yv = 0.f;
    if (lane < 30) {
        fvs = g_fvs[b * 30 + lane];
        fps = g_fps[b * 30 + lane];
        fvd = g_fvd[b * 30 + lane];
        fpd = g_fpd[b * 30 + lane];
        yv  = g_y30[b * 30 + lane];
    }

    float h1 = (lane < 30) ? bsp_s[lane] : 0.f;
    float h2 = h1;
    for (int i = 0; i < 30; i++) {
        float av = __shfl_sync(0xffffffffu, fvs, i);
        float bv = __shfl_sync(0xffffffffu, fps, i);
        float wv = (lane < 30) ? Wsp_s[i * 30 + lane] : 0.f;
        h1 = fmaf(av, wv, h1);
        h2 = fmaf(bv, wv, h2);
    }

    const int   pr = pairs[b];
    const float pf = (float)pr;
    const float h12 = h1 + h2;
    float m1 = fmaxf(h12, fmaxf(h1, h2));
    float lse1 = m1 + logf(2.f * expf(h12 - m1) + expf(h1 - m1) + expf(h2 - m1));
    float m2 = fmaxf(0.f, fmaxf(h1, h2));
    float lse2 = m2 + logf(2.f * expf(0.f - m2) + expf(h1 - m2) + expf(h2 - m2));
    const float favg = pf * (lse1 - lse2) + (1.f - pf) * h2;

    if (lane < 30) {
        ain[warp][0][lane] = fpd;
        ain[warp][1][lane] = favg;
        ain[warp][2][lane] = yv;
        ain[warp][3][lane] = fvd;
    }
    __syncwarp();

    float r[4][6];
#pragma unroll
    for (int g = 0; g < 6; g++) {
        float s0 = ba_s[g * 32 + lane], s1 = s0, s2 = s0, s3 = s0;
        for (int i = 0; i < 30; i++) {
            const float wv = Wa_s[i * 192 + g * 32 + lane];
            s0 = fmaf(ain[warp][0][i], wv, s0);
            s1 = fmaf(ain[warp][1][i], wv, s1);
            s2 = fmaf(ain[warp][2][i], wv, s2);
            s3 = fmaf(ain[warp][3][i], wv, s3);
        }
        r[0][g] = s0; r[1][g] = s1; r[2][g] = s2; r[3][g] = s3;
    }

    const float qsum3 = r[0][0] + r[1][0] + r[2][0];
    const float qm = pf * 0.25f * (qsum3 + r[3][0]) + (1.f - pf) * (qsum3 * (1.f / 3.f));

    float lg[4][4];
#pragma unroll
    for (int n = 0; n < 4; n++) {
#pragma unroll
        for (int t = 0; t < 4; t++) {
            float p = r[t][2 + n] * qm;
#pragma unroll
            for (int off = 16; off; off >>= 1) p += __shfl_xor_sync(0xffffffffu, p, off);
            lg[n][t] = p * 0.17677669529663687f;
        }
    }

#pragma unroll
    for (int n = 0; n < 4; n++) {
        const float l0 = lg[n][0], l1 = lg[n][1], l2 = lg[n][2], l3 = lg[n][3];
        float m = fmaxf(fmaxf(l0, l1), l2);
        if (pr) m = fmaxf(m, l3);
        const float e0 = expf(l0 - m), e1 = expf(l1 - m), e2 = expf(l2 - m);
        const float e3 = pr ? expf(l3 - m) : 0.f;
        const float inv = 1.f / (e0 + e1 + e2 + e3);
        const float ff = (e0 * r[0][1] + e1 * r[1][1] + e2 * r[2][1] + e3 * r[3][1]) * inv;
        float p = ff * Wf_s[lane * 4 + n];
#pragma unroll
        for (int off = 16; off; off >>= 1) p += __shfl_xor_sync(0xffffffffu, p, off);
        if (lane == 0) out[b * 4 + n] = p + bf_s[n];
    }
}

// =======================================================================
extern "C" void kernel_launch(void* const* d_in, const int* in_sizes, int n_in,
                              void* d_out, int out_size)
{
    (void)in_sizes; (void)n_in; (void)out_size;
    const int*   pairs = (const int*)d_in[0];
    const float* S_V  = (const float*)d_in[1];
    const float* S_P  = (const float*)d_in[2];
    const float* S_P1 = (const float*)d_in[3];
    const float* Wc_v = (const float*)d_in[4];  const float* bc_v = (const float*)d_in[5];
    const float* Ws_v = (const float*)d_in[6];  const float* bs_v = (const float*)d_in[7];
    const float* Wd_v = (const float*)d_in[8];  const float* bd_v = (const float*)d_in[9];
    const float* Wc_p = (const float*)d_in[10]; const float* bc_p = (const float*)d_in[11];
    const float* Ws_p = (const float*)d_in[12]; const float* bs_p = (const float*)d_in[13];
    const float* Wd_p = (const float*)d_in[14]; const float* bd_p = (const float*)d_in[15];
    const float* Wsp  = (const float*)d_in[16]; const float* bsp  = (const float*)d_in[17];
    const float* W1   = (const float*)d_in[18]; const float* b1   = (const float*)d_in[19];
    const float* W2   = (const float*)d_in[20]; const float* b2   = (const float*)d_in[21];
    const float* Wa   = (const float*)d_in[22]; const float* ba   = (const float*)d_in[23];
    const float* Wf   = (const float*)d_in[24]; const float* bf   = (const float*)d_in[25];
    float* out = (float*)d_out;

    cudaFuncSetAttribute(phys_kernel, cudaFuncAttributeMaxDynamicSharedMemorySize,
                         PHYS_SMEM);

    prep_w2t<<<80, 256>>>(W2);
    encode_kernel<<<dim3(NB, 2), 256>>>(S_V, S_P,
                                        Wc_v, bc_v, Ws_v, bs_v, Wd_v, bd_v,
                                        Wc_p, bc_p, Ws_p, bs_p, Wd_p, bd_p);
    phys_kernel<<<NB, 512, PHYS_SMEM>>>(S_P1, W1, b1, b2);
    fuse_kernel<<<NB / 8, 256>>>(pairs, Wsp, bsp, Wa, ba, Wf, bf, out);
}

// round 10
// speedup vs baseline: 1.2769x; 1.2769x over previous
#include <cuda_runtime.h>
#include <cuda_bf16.h>
#include <math.h>
#include <stdint.h>

#define NB 4096
#define FEATN 30

// ---------------- scratch (static device globals; no allocation) ----------------
__device__ float g_fvs[NB * FEATN];
__device__ float g_fvd[NB * FEATN];
__device__ float g_fps[NB * FEATN];
__device__ float g_fpd[NB * FEATN];
__device__ float g_y30[NB * FEATN];
// conv2 weight tiles, bf16 hi/lo, SW128-swizzled images: 10 tiles x 4096 B
// tiles 0..4 = Wh for k=0..4 ; tiles 5..9 = Wl for k=0..4. Tile: [n=32][c=64] bf16.
__device__ __align__(16) unsigned char g_w2t[10 * 4096];

// ---------------- f32x2 helpers ----------------
typedef unsigned long long ull_t;
__device__ __forceinline__ ull_t f2pack(float lo, float hi) {
    ull_t r; asm("mov.b64 %0, {%1,%2};" : "=l"(r) : "f"(lo), "f"(hi)); return r;
}
__device__ __forceinline__ ull_t f2dup(float v) { return f2pack(v, v); }
__device__ __forceinline__ void f2fma(ull_t& d, ull_t a, ull_t b) {
    asm("fma.rn.f32x2 %0, %1, %2, %0;" : "+l"(d) : "l"(a), "l"(b));
}
__device__ __forceinline__ void f2unpack(ull_t v, float& lo, float& hi) {
    asm("mov.b64 {%0,%1}, %2;" : "=f"(lo), "=f"(hi) : "l"(v));
}

// ---------------- warp-MMA helpers (sm_80-path, legal on compute_103) ----------
__device__ __forceinline__ uint32_t smem_u32(const void* p) {
    uint32_t a;
    asm("{ .reg .u64 t; cvta.to.shared.u64 t, %1; cvt.u32.u64 %0, t; }" : "=r"(a) : "l"(p));
    return a;
}
__device__ __forceinline__ uint32_t sw128(uint32_t o) { return o ^ ((o >> 3) & 0x70); }

__device__ __forceinline__ void ldmx4(uint32_t* r, uint32_t addr) {
    asm volatile("ldmatrix.sync.aligned.m8n8.x4.shared.b16 {%0,%1,%2,%3}, [%4];"
                 : "=r"(r[0]), "=r"(r[1]), "=r"(r[2]), "=r"(r[3]) : "r"(addr));
}
__device__ __forceinline__ void ldmx2(uint32_t* r, uint32_t addr) {
    asm volatile("ldmatrix.sync.aligned.m8n8.x2.shared.b16 {%0,%1}, [%2];"
                 : "=r"(r[0]), "=r"(r[1]) : "r"(addr));
}
__device__ __forceinline__ void mma16816(float* d, const uint32_t* a, const uint32_t* b) {
    asm volatile("mma.sync.aligned.m16n8k16.row.col.f32.bf16.bf16.f32 "
                 "{%0,%1,%2,%3}, {%4,%5,%6,%7}, {%8,%9}, {%0,%1,%2,%3};"
                 : "+f"(d[0]), "+f"(d[1]), "+f"(d[2]), "+f"(d[3])
                 : "r"(a[0]), "r"(a[1]), "r"(a[2]), "r"(a[3]), "r"(b[0]), "r"(b[1]));
}

// =======================================================================
// Prep: build bf16 hi/lo SW128 tile images of conv2 weights.
// W2: [30][64][5] row-major.  Tile (h*5+k): byte sw128(n*128 + c*2) = bf16.
// =======================================================================
__global__ void prep_w2t(const float* __restrict__ W2) {
    int i = blockIdx.x * 256 + threadIdx.x;       // 10*32*64 = 20480
    if (i < 20480) {
        int tile = i >> 11;                        // 0..9
        int rem  = i & 2047;
        int n = rem >> 6, c = rem & 63;
        int half = tile / 5, k = tile % 5;
        float w = (n < 30) ? W2[n * 320 + c * 5 + k] : 0.f;
        __nv_bfloat16 wh = __float2bfloat16(w);
        __nv_bfloat16 val = half ? __float2bfloat16(w - __bfloat162float(wh)) : wh;
        *reinterpret_cast<__nv_bfloat16*>(
            g_w2t + tile * 4096 + sw128((uint32_t)(n * 128 + c * 2))) = val;
    }
}

// =======================================================================
// Encode kernel (unchanged): conv1d(3->64,K=3)+ReLU+mean + 2 heads.
// =======================================================================
__global__ __launch_bounds__(256) void encode_kernel(
    const float* __restrict__ S_V, const float* __restrict__ S_P,
    const float* __restrict__ Wc_v, const float* __restrict__ bc_v,
    const float* __restrict__ Ws_v, const float* __restrict__ bs_v,
    const float* __restrict__ Wd_v, const float* __restrict__ bd_v,
    const float* __restrict__ Wc_p, const float* __restrict__ bc_p,
    const float* __restrict__ Ws_p, const float* __restrict__ bs_p,
    const float* __restrict__ Wd_p, const float* __restrict__ bd_p)
{
    __shared__ __align__(16) float xs[3][1032];
    __shared__ float part[64][9];
    __shared__ float hsh[64];

    const int tid = threadIdx.x;
    const int b   = blockIdx.x;
    const int mo  = blockIdx.y;

    const float* S   = mo ? S_P  : S_V;
    const float* Wc  = mo ? Wc_p : Wc_v;
    const float* bc  = mo ? bc_p : bc_v;
    const float* Ws  = mo ? Ws_p : Ws_v;
    const float* bsv = mo ? bs_p : bs_v;
    const float* Wd  = mo ? Wd_p : Wd_v;
    const float* bdv = mo ? bd_p : bd_v;
    float* fs_out = mo ? g_fps : g_fvs;
    float* fd_out = mo ? g_fpd : g_fvd;

    if (tid < 24) xs[tid / 8][1024 + (tid & 7)] = 0.f;
    const float* Sb = S + (size_t)b * 3072;
    for (int i = tid; i < 3072; i += 256) xs[i % 3][i / 3] = Sb[i];
    __syncthreads();

    const int pg = tid >> 3;
    const int tg = tid & 7;
    const int o0 = pg * 2;

    ull_t WU[9];
#pragma unroll
    for (int i = 0; i < 9; i++)
        WU[i] = f2pack(Wc[o0 * 9 + i], Wc[o0 * 9 + 9 + i]);
    const ull_t Bp = f2pack(bc[o0], bc[o0 + 1]);

    float s0 = 0.f, s1 = 0.f;
    for (int m = 0; m < 32; m++) {
        const int t0 = 4 * tg + 32 * m;
        ull_t A[4] = {Bp, Bp, Bp, Bp};
#pragma unroll
        for (int c = 0; c < 3; c++) {
            float4 qa = *(const float4*)&xs[c][t0];
            float2 qb = *(const float2*)&xs[c][t0 + 4];
            ull_t X[6];
            X[0] = f2dup(qa.x); X[1] = f2dup(qa.y); X[2] = f2dup(qa.z);
            X[3] = f2dup(qa.w); X[4] = f2dup(qb.x); X[5] = f2dup(qb.y);
#pragma unroll
            for (int k = 0; k < 3; k++) {
                const ull_t W = WU[c * 3 + k];
#pragma unroll
                for (int p = 0; p < 4; p++) f2fma(A[p], X[p + k], W);
            }
        }
        float u[4], v[4];
#pragma unroll
        for (int p = 0; p < 4; p++) f2unpack(A[p], u[p], v[p]);
        if (t0 + 3 < 1022) {
#pragma unroll
            for (int p = 0; p < 4; p++) { s0 += fmaxf(u[p], 0.f); s1 += fmaxf(v[p], 0.f); }
        } else {
#pragma unroll
            for (int p = 0; p < 4; p++)
                if (t0 + p < 1022) { s0 += fmaxf(u[p], 0.f); s1 += fmaxf(v[p], 0.f); }
        }
    }
    part[o0][tg] = s0; part[o0 + 1][tg] = s1;
    __syncthreads();

    if (tid < 64) {
        float s = 0.f;
#pragma unroll
        for (int g = 0; g < 8; g++) s += part[tid][g];
        hsh[tid] = s * (1.f / 1022.f);
    }
    __syncthreads();

    if (tid < 60) {
        const int  j2 = tid % 30;
        const bool first = tid < 30;
        const float* Wm = first ? Ws : Wd;
        float s = first ? bsv[j2] : bdv[j2];
        for (int i = 0; i < 64; i++) s = fmaf(hsh[i], Wm[i * 30 + j2], s);
        if (first) fs_out[b * 30 + j2] = s;
        else       fd_out[b * 30 + j2] = s;
    }
}

// =======================================================================
// Physical-model kernel:
//   conv1 (f32x2) -> p1 bf16 hi/lo, t-major [256][64] SW128 smem
//   conv2 via warp mma.sync.m16n8k16 bf16 (3-product emulated fp32):
//     shift-k applied by offsetting the A-fragment row base; all 5 shifts
//     accumulate in MMA register accumulators (no smem RMW, no inner syncs).
//   maxpool4 + mean -> y30.
// One block per sample, 512 threads, ~108 KB smem -> 2 CTAs/SM.
// =======================================================================
#define XS_OFF      0u        /* floats, aliases WBUF (dead after conv1) */
#define WBUF_OFF    0u        /* 40960 B, 10 x 4096 */
#define CO_OFF      0u        /* conv_out aliases WBUF after MMA phase: 248 x 33 fl */
#define P1H_OFF     40960u    /* 32768 B */
#define P1L_OFF     73728u    /* 32768 B */
#define PART_OFF    106496u   /* 480 floats */
#define PHYS_SMEM   108416
#define COSTR       33

__global__ __launch_bounds__(512, 2) void phys_kernel(
    const float* __restrict__ S_P1,
    const float* __restrict__ W1, const float* __restrict__ b1,
    const float* __restrict__ b2)
{
    extern __shared__ __align__(16) unsigned char smraw[];
    const uint32_t smb = smem_u32(smraw);
    float* xs   = (float*)(smraw + XS_OFF);
    float* part = (float*)(smraw + PART_OFF);

    const int tid  = threadIdx.x;
    const int b    = blockIdx.x;
    const int wid  = tid >> 5;
    const int lane = tid & 31;

    const float* Sb = S_P1 + (size_t)b * 3072;
    for (int i = tid; i < 3072; i += 512) xs[(i % 3) * 1032 + i / 3] = Sb[i];
    __syncthreads();

    // -------- conv1 (K=5, C=3, O=64) + maxpool4, o-pair f32x2, bf16 hi/lo out --
    {
        const int pg = tid >> 4;
        const int tg = tid & 15;
        const int o0 = pg * 2;
        ull_t WU[15];
#pragma unroll
        for (int i = 0; i < 15; i++)
            WU[i] = f2pack(W1[o0 * 15 + i], W1[o0 * 15 + 15 + i]);
        const ull_t Bp = f2pack(b1[o0], b1[o0 + 1]);

        for (int m = 0; m < 16; m++) {
            const int j = tg + m * 16;
            if (j < 255) {
                const int t0 = 4 * j;
                ull_t A[4] = {Bp, Bp, Bp, Bp};
#pragma unroll
                for (int c = 0; c < 3; c++) {
                    const float* xr = xs + c * 1032 + t0;
                    float4 qa = *(const float4*)xr;
                    float4 qb = *(const float4*)(xr + 4);
                    ull_t X[8];
                    X[0] = f2dup(qa.x); X[1] = f2dup(qa.y); X[2] = f2dup(qa.z);
                    X[3] = f2dup(qa.w); X[4] = f2dup(qb.x); X[5] = f2dup(qb.y);
                    X[6] = f2dup(qb.z); X[7] = f2dup(qb.w);
#pragma unroll
                    for (int k = 0; k < 5; k++) {
                        const ull_t W = WU[c * 5 + k];
#pragma unroll
                        for (int p = 0; p < 4; p++) f2fma(A[p], X[p + k], W);
                    }
                }
                float u[4], v[4];
#pragma unroll
                for (int p = 0; p < 4; p++) f2unpack(A[p], u[p], v[p]);
                const float pa = fmaxf(fmaxf(u[0], u[1]), fmaxf(u[2], u[3]));
                const float pb = fmaxf(fmaxf(v[0], v[1]), fmaxf(v[2], v[3]));
                __nv_bfloat16 h0 = __float2bfloat16(pa);
                __nv_bfloat16 h1 = __float2bfloat16(pb);
                __nv_bfloat16 l0 = __float2bfloat16(pa - __bfloat162float(h0));
                __nv_bfloat16 l1 = __float2bfloat16(pb - __bfloat162float(h1));
                const uint32_t off = sw128((uint32_t)(j * 128 + o0 * 2));
                *reinterpret_cast<__nv_bfloat162*>(smraw + P1H_OFF + off) =
                    __halves2bfloat162(h0, h1);
                *reinterpret_cast<__nv_bfloat162*>(smraw + P1L_OFF + off) =
                    __halves2bfloat162(l0, l1);
            }
        }
    }
    // zero p1 row 255 (unwritten)
    if (tid < 32) {
        const uint32_t off = sw128((uint32_t)(255 * 128 + tid * 4));
        *reinterpret_cast<uint32_t*>(smraw + P1H_OFF + off) = 0u;
        *reinterpret_cast<uint32_t*>(smraw + P1L_OFF + off) = 0u;
    }
    __syncthreads();

    // -------- copy conv2 weight tiles into smem (xs region is dead now) -------
    {
        const uint4* gw = (const uint4*)g_w2t;
        uint4* swp = (uint4*)(smraw + WBUF_OFF);
        for (int i = tid; i < 2560; i += 512) swp[i] = gw[i];
    }
    __syncthreads();

    // -------- conv2: shifts folded into A row base, register accumulation ----
    // warp w computes conv_out rows [w*16, w*16+16), all 30 n (4 n-tiles)
    const uint32_t a_rowl = (uint32_t)(lane & 15);
    const uint32_t a_koff = (uint32_t)((lane >> 4) * 16);
    const uint32_t bn     = (uint32_t)(lane & 7) * 128;
    const uint32_t bkoff  = (uint32_t)((lane >> 3) & 1) * 16;

    float d[4][4];
#pragma unroll
    for (int nt = 0; nt < 4; nt++)
#pragma unroll
        for (int i = 0; i < 4; i++) d[nt][i] = 0.f;

#pragma unroll
    for (int k = 0; k < 5; k++) {
        const uint32_t bbase_h = smb + WBUF_OFF + (uint32_t)k * 4096;
        const uint32_t bbase_l = bbase_h + 5u * 4096;
        const uint32_t arow    = (uint32_t)(wid * 16 + k) + a_rowl;
#pragma unroll
        for (int ks = 0; ks < 4; ks++) {
            uint32_t Ah[4], Al[4];
            const uint32_t ao = sw128(arow * 128 + (uint32_t)ks * 32 + a_koff);
            ldmx4(Ah, smb + P1H_OFF + ao);
            ldmx4(Al, smb + P1L_OFF + ao);
#pragma unroll
            for (int nt = 0; nt < 4; nt++) {
                const uint32_t bo =
                    sw128(bn + (uint32_t)nt * 1024 + (uint32_t)ks * 32 + bkoff);
                uint32_t bh[2], bl[2];
                ldmx2(bh, bbase_h + bo);
                ldmx2(bl, bbase_l + bo);
                mma16816(d[nt], Ah, bh);
                mma16816(d[nt], Al, bh);
                mma16816(d[nt], Ah, bl);
            }
        }
    }
    __syncthreads();   // all WBUF reads complete; conv_out aliases WBUF

    {
        float* conv_out = (float*)(smraw + CO_OFF);
        const int t0 = wid * 16 + (lane >> 2);
        const int t1 = t0 + 8;
        const int n0 = (lane & 3) * 2;
#pragma unroll
        for (int nt = 0; nt < 4; nt++) {
            const int n = nt * 8 + n0;
            if (t0 < 248) {
                conv_out[t0 * COSTR + n]     = d[nt][0];
                conv_out[t0 * COSTR + n + 1] = d[nt][1];
            }
            if (t1 < 248) {
                conv_out[t1 * COSTR + n]     = d[nt][2];
                conv_out[t1 * COSTR + n + 1] = d[nt][3];
            }
        }
    }
    __syncthreads();

    // -------- maxpool4 (62 windows over t=0..247) + mean ----------------------
    {
        float* conv_out = (float*)(smraw + CO_OFF);
        if (tid < 480) {
            const int n = tid >> 4, jg = tid & 15;
            float s = 0.f;
#pragma unroll
            for (int j = jg; j < 62; j += 16) {
                const float* cr = conv_out + 4 * j * COSTR + n;
                float mx = fmaxf(fmaxf(cr[0], cr[COSTR]),
                                 fmaxf(cr[2 * COSTR], cr[3 * COSTR]));
                s += mx;
            }
            part[n * 16 + jg] = s;
        }
    }
    __syncthreads();
    if (tid < 30) {
        float s = 0.f;
#pragma unroll
        for (int g = 0; g < 16; g++) s += part[tid * 16 + g];
        g_y30[b * 30 + tid] = s * (1.f / 62.f) + b2[tid];
    }
}

// =======================================================================
// Fusion kernel (unchanged).
// =======================================================================
__global__ __launch_bounds__(256) void fuse_kernel(
    const int* __restrict__ pairs,
    const float* __restrict__ Wsp, const float* __restrict__ bsp,
    const float* __restrict__ Wa, const float* __restrict__ ba,
    const float* __restrict__ Wf, const float* __restrict__ bf,
    float* __restrict__ out)
{
    __shared__ float Wsp_s[900], bsp_s[30], Wa_s[5760], ba_s[192], Wf_s[128], bf_s[4];
    __shared__ float ain[8][4][32];

    const int tid = threadIdx.x;
    for (int i = tid; i < 900; i += 256) Wsp_s[i] = Wsp[i];
    for (int i = tid; i < 5760; i += 256) Wa_s[i] = Wa[i];
    if (tid < 30)  bsp_s[tid] = bsp[tid];
    if (tid < 192) ba_s[tid]  = ba[tid];
    if (tid < 128) Wf_s[tid]  = Wf[tid];
    if (tid < 4)   bf_s[tid]  = bf[tid];
    __syncthreads();

    const int warp = tid >> 5, lane = tid & 31;
    const int b = blockIdx.x * 8 + warp;

    float fvs = 0.f, fps = 0.f, fvd = 0.f, fpd = 0.f, yv = 0.f;
    if (lane < 30) {
        fvs = g_fvs[b * 30 + lane];
        fps = g_fps[b * 30 + lane];
        fvd = g_fvd[b * 30 + lane];
        fpd = g_fpd[b * 30 + lane];
        yv  = g_y30[b * 30 + lane];
    }

    float h1 = (lane < 30) ? bsp_s[lane] : 0.f;
    float h2 = h1;
    for (int i = 0; i < 30; i++) {
        float av = __shfl_sync(0xffffffffu, fvs, i);
        float bv = __shfl_sync(0xffffffffu, fps, i);
        float wv = (lane < 30) ? Wsp_s[i * 30 + lane] : 0.f;
        h1 = fmaf(av, wv, h1);
        h2 = fmaf(bv, wv, h2);
    }

    const int   pr = pairs[b];
    const float pf = (float)pr;
    const float h12 = h1 + h2;
    float m1 = fmaxf(h12, fmaxf(h1, h2));
    float lse1 = m1 + logf(2.f * expf(h12 - m1) + expf(h1 - m1) + expf(h2 - m1));
    float m2 = fmaxf(0.f, fmaxf(h1, h2));
    float lse2 = m2 + logf(2.f * expf(0.f - m2) + expf(h1 - m2) + expf(h2 - m2));
    const float favg = pf * (lse1 - lse2) + (1.f - pf) * h2;

    if (lane < 30) {
        ain[warp][0][lane] = fpd;
        ain[warp][1][lane] = favg;
        ain[warp][2][lane] = yv;
        ain[warp][3][lane] = fvd;
    }
    __syncwarp();

    float r[4][6];
#pragma unroll
    for (int g = 0; g < 6; g++) {
        float s0 = ba_s[g * 32 + lane], s1 = s0, s2 = s0, s3 = s0;
        for (int i = 0; i < 30; i++) {
            const float wv = Wa_s[i * 192 + g * 32 + lane];
            s0 = fmaf(ain[warp][0][i], wv, s0);
            s1 = fmaf(ain[warp][1][i], wv, s1);
            s2 = fmaf(ain[warp][2][i], wv, s2);
            s3 = fmaf(ain[warp][3][i], wv, s3);
        }
        r[0][g] = s0; r[1][g] = s1; r[2][g] = s2; r[3][g] = s3;
    }

    const float qsum3 = r[0][0] + r[1][0] + r[2][0];
    const float qm = pf * 0.25f * (qsum3 + r[3][0]) + (1.f - pf) * (qsum3 * (1.f / 3.f));

    float lg[4][4];
#pragma unroll
    for (int n = 0; n < 4; n++) {
#pragma unroll
        for (int t = 0; t < 4; t++) {
            float p = r[t][2 + n] * qm;
#pragma unroll
            for (int off = 16; off; off >>= 1) p += __shfl_xor_sync(0xffffffffu, p, off);
            lg[n][t] = p * 0.17677669529663687f;
        }
    }

#pragma unroll
    for (int n = 0; n < 4; n++) {
        const float l0 = lg[n][0], l1 = lg[n][1], l2 = lg[n][2], l3 = lg[n][3];
        float m = fmaxf(fmaxf(l0, l1), l2);
        if (pr) m = fmaxf(m, l3);
        const float e0 = expf(l0 - m), e1 = expf(l1 - m), e2 = expf(l2 - m);
        const float e3 = pr ? expf(l3 - m) : 0.f;
        const float inv = 1.f / (e0 + e1 + e2 + e3);
        const float ff = (e0 * r[0][1] + e1 * r[1][1] + e2 * r[2][1] + e3 * r[3][1]) * inv;
        float p = ff * Wf_s[lane * 4 + n];
#pragma unroll
        for (int off = 16; off; off >>= 1) p += __shfl_xor_sync(0xffffffffu, p, off);
        if (lane == 0) out[b * 4 + n] = p + bf_s[n];
    }
}

// =======================================================================
extern "C" void kernel_launch(void* const* d_in, const int* in_sizes, int n_in,
                              void* d_out, int out_size)
{
    (void)in_sizes; (void)n_in; (void)out_size;
    const int*   pairs = (const int*)d_in[0];
    const float* S_V  = (const float*)d_in[1];
    const float* S_P  = (const float*)d_in[2];
    const float* S_P1 = (const float*)d_in[3];
    const float* Wc_v = (const float*)d_in[4];  const float* bc_v = (const float*)d_in[5];
    const float* Ws_v = (const float*)d_in[6];  const float* bs_v = (const float*)d_in[7];
    const float* Wd_v = (const float*)d_in[8];  const float* bd_v = (const float*)d_in[9];
    const float* Wc_p = (const float*)d_in[10]; const float* bc_p = (const float*)d_in[11];
    const float* Ws_p = (const float*)d_in[12]; const float* bs_p = (const float*)d_in[13];
    const float* Wd_p = (const float*)d_in[14]; const float* bd_p = (const float*)d_in[15];
    const float* Wsp  = (const float*)d_in[16]; const float* bsp  = (const float*)d_in[17];
    const float* W1   = (const float*)d_in[18]; const float* b1   = (const float*)d_in[19];
    const float* W2   = (const float*)d_in[20]; const float* b2   = (const float*)d_in[21];
    const float* Wa   = (const float*)d_in[22]; const float* ba   = (const float*)d_in[23];
    const float* Wf   = (const float*)d_in[24]; const float* bf   = (const float*)d_in[25];
    float* out = (float*)d_out;

    cudaFuncSetAttribute(phys_kernel, cudaFuncAttributeMaxDynamicSharedMemorySize,
                         PHYS_SMEM);

    prep_w2t<<<80, 256>>>(W2);
    encode_kernel<<<dim3(NB, 2), 256>>>(S_V, S_P,
                                        Wc_v, bc_v, Ws_v, bs_v, Wd_v, bd_v,
                                        Wc_p, bc_p, Ws_p, bs_p, Wd_p, bd_p);
    phys_kernel<<<NB, 512, PHYS_SMEM>>>(S_P1, W1, b1, b2);
    fuse_kernel<<<NB / 8, 256>>>(pairs, Wsp, bsp, Wa, ba, Wf, bf, out);
}